// round 16
// baseline (speedup 1.0000x reference)
#include <cuda_runtime.h>

// Problem shapes (compile-time constants)
#define BATCH 8
#define NC    28
#define HH    256
#define WCC   310
#define WPP   256

static constexpr int HWC = HH * WCC;                 // 79360 (even)
static constexpr int HWP = HH * WPP;                 // 65536
static constexpr int NPIX_C = BATCH * HWC;           // 634880
static constexpr int NPIX_P = BATCH * HWP;           // 524288
static constexpr int XC_ELEMS = BATCH * NC * HWC;    // 17,776,640

// Schedule: 16 groups x 283 blocks (155 xc + 128 xp per group; each group =
// half a batch image in both domains). R16 refinement: instead of running
// the 155 xc blocks then the 128 xp blocks back-to-back, interleave them
// Bresenham-style (ratio 155:128) so the resident CTA mix is uniform in
// time and the xp path's shifted-z reads trail the xc path's z loads by
// ~2 blocks instead of ~155 (warmer L2). Traffic unchanged.
static constexpr int XC_BLK_PER_GRP = 155;
static constexpr int XP_BLK_PER_GRP = 128;
static constexpr int GRP_BLKS = 283;

__global__ void __launch_bounds__(128, 3)
dp_fused_kernel(const float* __restrict__ z,
                const float* __restrict__ yc,
                const float* __restrict__ phi_c,
                const float* __restrict__ yp,
                const float* __restrict__ phi_p,
                const float* __restrict__ xc_k_1,
                const float* __restrict__ xp_k_1,
                const float* __restrict__ mu,
                const float* __restrict__ mu_c,
                const float* __restrict__ mu_p,
                float* __restrict__ out)
{
    const int g = blockIdx.x / GRP_BLKS;
    const int j = blockIdx.x - g * GRP_BLKS;
    const float mu_ = mu[0];

    // Bresenham split within the group: position j in [0,283) is an xp slot
    // iff floor((j+1)*128/283) > floor(j*128/283). xp slots: 128, xc: 155.
    const int xp_before = (j * XP_BLK_PER_GRP) / GRP_BLKS;
    const int xp_after  = ((j + 1) * XP_BLK_PER_GRP) / GRP_BLKS;
    const bool is_xp = (xp_after > xp_before);

    if (!is_xp) {
        // ---------------- xc update (coded domain, W=310) ----------------
        const int unit = g * XC_BLK_PER_GRP + (j - xp_before);
        const int pix  = (unit * 128 + threadIdx.x) * 2;  // even, < NPIX_C
        const float muc = mu_c[0];
        const float inv = 1.f / (mu_ + muc);
        const float wA  = muc * inv;
        const float wz  = mu_ * inv;
        const int b    = pix / HWC;
        const int rem  = pix - b * HWC;          // even
        const int base = b * (NC * HWC) + rem;   // 8B aligned

        // Hoisted: overlap y's DRAM latency with the channel-load burst.
        const float2 y2 = *(const float2*)(yc + pix);

        float2 mr[NC], pr[NC];
        float2 s  = make_float2(0.f, 0.f);
        float2 am = make_float2(0.f, 0.f);
        #pragma unroll
        for (int c = 0; c < NC; ++c) {
            const int o = base + c * HWC;
            const float2 zv = *(const float2*)(z      + o);
            const float2 pv = *(const float2*)(phi_c  + o);
            const float2 xv = *(const float2*)(xp_k_1 + o);
            float2 m;
            m.x = fmaf(wz, xv.x, wA * zv.x);
            m.y = fmaf(wz, xv.y, wA * zv.y);
            mr[c] = m; pr[c] = pv;
            s.x  = fmaf(pv.x, pv.x, s.x);
            s.y  = fmaf(pv.y, pv.y, s.y);
            am.x = fmaf(m.x, pv.x, am.x);
            am.y = fmaf(m.y, pv.y, am.y);
        }
        if (s.x == 0.f) s.x = 1.f;
        if (s.y == 0.f) s.y = 1.f;
        float2 t;
        t.x = __fdividef(y2.x - am.x, mu_ + muc + s.x);
        t.y = __fdividef(y2.y - am.y, mu_ + muc + s.y);

        #pragma unroll
        for (int c = 0; c < NC; ++c) {
            float2 o2;
            o2.x = fmaf(t.x, pr[c].x, mr[c].x);
            o2.y = fmaf(t.y, pr[c].y, mr[c].y);
            *(float2*)(out + base + c * HWC) = o2;
        }
    } else {
        // ---------------- xp update (PAN domain, W=256) ----------------
        const int unit = g * XP_BLK_PER_GRP + xp_before;
        const int pix  = (unit * 128 + threadIdx.x) * 2;  // even, < NPIX_P
        const float mup = mu_p[0];
        const float inv = 1.f / (mu_ + mup);
        const float wA  = mup * inv;
        const float wz  = mu_ * inv;
        const int b   = pix / HWP;
        const int rem = pix - b * HWP;           // even
        const int h   = rem >> 8;                // WP = 256
        const int w   = rem & 255;               // even
        const int basep = b * (NC * HWP) + rem;                 // phi_p / xc_k_1 / out
        const int basec = b * (NC * HWC) + h * WCC + w;         // z (shifted), even

        const float2 y2 = *(const float2*)(yp + pix);  // hoisted

        float2 mr[NC], pr[NC];
        float2 s  = make_float2(0.f, 0.f);
        float2 am = make_float2(0.f, 0.f);
        #pragma unroll
        for (int c = 0; c < NC; ++c) {
            // shift_back: z[b,c,h,w+2c] and z[b,c,h,w+1+2c]; w+1+2c <= 309, no wrap.
            const float2 zv = *(const float2*)(z + basec + c * HWC + 2 * c);
            const int  o  = basep + c * HWP;
            const float2 pv = *(const float2*)(phi_p  + o);
            const float2 xv = *(const float2*)(xc_k_1 + o);
            float2 m;
            m.x = fmaf(wz, xv.x, wA * zv.x);
            m.y = fmaf(wz, xv.y, wA * zv.y);
            mr[c] = m; pr[c] = pv;
            s.x  = fmaf(pv.x, pv.x, s.x);
            s.y  = fmaf(pv.y, pv.y, s.y);
            am.x = fmaf(m.x, pv.x, am.x);
            am.y = fmaf(m.y, pv.y, am.y);
        }
        if (s.x == 0.f) s.x = 1.f;
        if (s.y == 0.f) s.y = 1.f;
        float2 t;
        t.x = __fdividef(y2.x - am.x, mu_ + mup + s.x);
        t.y = __fdividef(y2.y - am.y, mu_ + mup + s.y);

        float* __restrict__ outp = out + XC_ELEMS;
        #pragma unroll
        for (int c = 0; c < NC; ++c) {
            float2 o2;
            o2.x = fmaf(t.x, pr[c].x, mr[c].x);
            o2.y = fmaf(t.y, pr[c].y, mr[c].y);
            *(float2*)(outp + basep + c * HWP) = o2;
        }
    }
}

extern "C" void kernel_launch(void* const* d_in, const int* in_sizes, int n_in,
                              void* d_out, int out_size)
{
    const float* z      = (const float*)d_in[0];
    const float* yc     = (const float*)d_in[1];
    const float* phi_c  = (const float*)d_in[2];
    const float* yp     = (const float*)d_in[3];
    const float* phi_p  = (const float*)d_in[4];
    const float* xc_k_1 = (const float*)d_in[5];
    const float* xp_k_1 = (const float*)d_in[6];
    const float* mu     = (const float*)d_in[7];
    const float* mu_c   = (const float*)d_in[8];
    const float* mu_p   = (const float*)d_in[9];
    float* out = (float*)d_out;

    const int blocks = (NPIX_C + NPIX_P) / 256;   // 4528 = 16 * 283
    dp_fused_kernel<<<blocks, 128>>>(z, yc, phi_c, yp, phi_p,
                                     xc_k_1, xp_k_1, mu, mu_c, mu_p, out);
}